// round 9
// baseline (speedup 1.0000x reference)
#include <cuda_runtime.h>

// out[b,i,h,w] = sum_j x[b,j,h,w] - x[b,i,h,w]
// x: fp32 [16, 256, 128, 128]
//
// R9: same deep-MLP recipe as R8 (CPT=16 channels x float4 per thread,
// 16 LDG.128 in flight per warp, __stcs streaming stores) but with
// 128-thread blocks -> 6 blocks/SM (80 regs x 128 thr x 6 = 61440 regs).
// Same ~196 KB reads in flight per SM as R7/R8, but SIX independent barrier
// domains per SM (vs 3) for the finest load/store phase staggering tested
// (R1: 1 dom = 66% DRAM, R2: 2 dom = 77%, R8: 3 dom = 80.6%).

constexpr int B_DIM  = 16;
constexpr int C_DIM  = 256;
constexpr int S_DIM  = 128 * 128;        // spatial per (b,c)
constexpr int GROUPS = 16;               // channel groups per block
constexpr int CPT    = C_DIM / GROUPS;   // 16 channels per thread
constexpr int LANES  = 8;                // float4 lanes per group
constexpr int VEC    = 4;                // floats per lane (float4)
constexpr int SPB    = LANES * VEC;      // 32 spatial positions per block
constexpr int THREADS = GROUPS * LANES;  // 128

__global__ __launch_bounds__(THREADS, 6)
void neighbour_channels_kernel(const float* __restrict__ x,
                               float* __restrict__ out)
{
    __shared__ float4 red[GROUPS][LANES];

    const int lane = threadIdx.x & (LANES - 1);
    const int grp  = threadIdx.x >> 3;           // 0..15

    const int tiles_per_b = S_DIM / SPB;         // 512
    const int tile = blockIdx.x % tiles_per_b;
    const int b    = blockIdx.x / tiles_per_b;

    const long long spatial = (long long)tile * SPB + lane * VEC;
    const long long base    = (long long)b * C_DIM * S_DIM
                            + (long long)grp * CPT * S_DIM
                            + spatial;

    const float4* __restrict__ xp = (const float4*)(x + base);

    // 16 independent LDG.128 per thread -> deep read queue.
    float4 v[CPT];
#pragma unroll
    for (int i = 0; i < CPT; ++i) {
        v[i] = xp[(long long)i * (S_DIM / 4)];
    }

    float4 sum = make_float4(0.0f, 0.0f, 0.0f, 0.0f);
#pragma unroll
    for (int i = 0; i < CPT; ++i) {
        sum.x += v[i].x;
        sum.y += v[i].y;
        sum.z += v[i].z;
        sum.w += v[i].w;
    }

    // Cross-group reduction: 16 partials per lane.
    red[grp][lane] = sum;
    __syncthreads();

    float4 total = make_float4(0.0f, 0.0f, 0.0f, 0.0f);
#pragma unroll
    for (int g = 0; g < GROUPS; ++g) {
        float4 p = red[g][lane];
        total.x += p.x;
        total.y += p.y;
        total.z += p.z;
        total.w += p.w;
    }

    // Streaming (evict-first) stores: drain writes promptly, keep L2 for reads.
    float4* __restrict__ op = (float4*)(out + base);
#pragma unroll
    for (int i = 0; i < CPT; ++i) {
        float4 o;
        o.x = total.x - v[i].x;
        o.y = total.y - v[i].y;
        o.z = total.z - v[i].z;
        o.w = total.w - v[i].w;
        __stcs(op + (long long)i * (S_DIM / 4), o);
    }
}

extern "C" void kernel_launch(void* const* d_in, const int* in_sizes, int n_in,
                              void* d_out, int out_size)
{
    const float* x = (const float*)d_in[0];
    float* out = (float*)d_out;

    const int grid = B_DIM * (S_DIM / SPB);  // 16 * 512 = 8192 blocks
    neighbour_channels_kernel<<<grid, THREADS>>>(x, out);
}